// round 12
// baseline (speedup 1.0000x reference)
#include <cuda_runtime.h>

#define N 4096
#define NITERS 300
#define NBLK 148
#define TPB 1024
#define SROWS 26
#define STRIPE (SROWS * NBLK)              // 3848 rows in smem chip-wide
#define SMEM_K (SROWS * N * 2)             // 212992 B bf16 stripe
#define SMEM_BYTES (SMEM_K + N * 4 + 256)  // + V[4096] f32 + sU/sred

__device__ unsigned short d_Kh[(size_t)N * N];  // K = bf16(2^(-k*C)), 32MB
__device__ float  d_T[2][N];                    // double-buffered column sums
__device__ double d_csum;
__device__ double d_emd;
__device__ float  d_k;                          // log2(e)/eps
__device__ unsigned int g_bar;
__device__ unsigned int g_epoch;

__device__ __forceinline__ float bfl(unsigned u) { return __uint_as_float(u << 16); }
__device__ __forceinline__ float bfh(unsigned u) { return __uint_as_float(u & 0xFFFF0000u); }

// ---------------------------------------------------------------- init
__global__ void k_init() {
    d_csum  = 0.0;
    d_emd   = 0.0;
    g_bar   = 0u;
    g_epoch = 0u;
}

// ---------------------------------------------------------------- csum
__global__ void k_sum(const float* __restrict__ x, const float* __restrict__ y) {
    __shared__ float sred[8];
    int i = blockIdx.x;
    float x0 = x[3 * i], x1 = x[3 * i + 1], x2 = x[3 * i + 2];
    float xx = x0 * x0 + x1 * x1 + x2 * x2;
    float acc = 0.0f;
    for (int j = threadIdx.x; j < N; j += 256) {
        float y0 = y[3 * j], y1 = y[3 * j + 1], y2 = y[3 * j + 2];
        float yy  = y0 * y0 + y1 * y1 + y2 * y2;
        float dot = x0 * y0 + x1 * y1 + x2 * y2;
        float d2  = xx + yy - 2.0f * dot;
        acc += sqrtf(fmaxf(d2, 0.0f) + 1e-12f);
    }
    for (int o = 16; o; o >>= 1) acc += __shfl_down_sync(0xffffffffu, acc, o);
    if ((threadIdx.x & 31) == 0) sred[threadIdx.x >> 5] = acc;
    __syncthreads();
    if (threadIdx.x < 8) {
        acc = sred[threadIdx.x];
        for (int o = 4; o; o >>= 1) acc += __shfl_down_sync(0xffu, acc, o);
        if (threadIdx.x == 0) atomicAdd(&d_csum, (double)acc);
    }
}

// ---------------------------------------------------------------- eps -> k
__global__ void k_eps() {
    double mean = d_csum / ((double)N * (double)N);
    d_k = (float)(1.4426950408889634 / (0.02 * mean));
}

// ---------------------------------------------------------------- build K = bf16(2^(-k*C))
__global__ void k_buildK(const float* __restrict__ x, const float* __restrict__ y) {
    int i = blockIdx.x;
    float k = d_k;
    float x0 = x[3 * i], x1 = x[3 * i + 1], x2 = x[3 * i + 2];
    float xx = x0 * x0 + x1 * x1 + x2 * x2;
    for (int j = threadIdx.x; j < N; j += 256) {
        float y0 = y[3 * j], y1 = y[3 * j + 1], y2 = y[3 * j + 2];
        float yy  = y0 * y0 + y1 * y1 + y2 * y2;
        float dot = x0 * y0 + x1 * y1 + x2 * y2;
        float d2  = xx + yy - 2.0f * dot;
        float c   = sqrtf(fmaxf(d2, 0.0f) + 1e-12f);
        unsigned u = __float_as_uint(exp2f(-k * c));
        unsigned r = (u + 0x7FFFu + ((u >> 16) & 1u)) >> 16;   // rne bf16
        d_Kh[(size_t)i * N + j] = (unsigned short)r;
    }
}

// ---------------------------------------------------------------- grid barrier
__device__ __forceinline__ void gsync(unsigned int& ep) {
    __syncthreads();
    if (threadIdx.x == 0) {
        unsigned int t;
        asm volatile("atom.add.release.gpu.u32 %0, [%1], 1;"
                     : "=r"(t) : "l"(&g_bar) : "memory");
        if (t == NBLK - 1) {
            g_bar = 0u;
            asm volatile("st.release.gpu.u32 [%0], %1;"
                         :: "l"(&g_epoch), "r"(ep + 1u) : "memory");
        } else {
            unsigned int v;
            do {
                asm volatile("ld.acquire.gpu.u32 %0, [%1];"
                             : "=r"(v) : "l"(&g_epoch) : "memory");
            } while (v == ep);
        }
    }
    ep++;
    __syncthreads();
}

// ---------------------------------------------------------------- persistent linear Sinkhorn, SMEM-resident stripe
__global__ void __launch_bounds__(TPB, 1) k_persist(float* __restrict__ out) {
    extern __shared__ char smem[];
    unsigned short* sK = (unsigned short*)smem;             // [SROWS][N] bf16
    float* sV  = (float*)(smem + SMEM_K);                   // [N]
    float* sU  = (float*)(smem + SMEM_K + N * 4);           // [32]
    float* sred = sU + 32;                                  // [32]

    const int tid = threadIdx.x;
    const int bid = blockIdx.x;
    const int wid = tid >> 5;
    const int ln  = tid & 31;
    const int zs  = (bid * N) / NBLK;                       // owned T slice
    const int ze  = ((bid + 1) * N) / NBLK;
    const int stray1 = STRIPE + bid;                        // 3848+bid (always < N)
    const int stray2 = STRIPE + NBLK + bid;                 // valid if < N
    unsigned int ep = 0u;

    // ---- prologue: stripe gmem->smem; T[0] = 4096 (v0 = 1)
    {
        const uint4* src = (const uint4*)(d_Kh + (size_t)(bid * SROWS) * N);
        uint4* dst = (uint4*)sK;
        for (int t = tid; t < SMEM_K / 16; t += TPB) dst[t] = src[t];
        int zi = zs + tid;
        if (zi < ze) __stcg(&d_T[0][zi], 4096.0f);
    }
    gsync(ep);

    for (int it = 0; it < NITERS; it++) {
        const int p = it & 1;
        const float* Tc = d_T[p];
        float*       Tn = d_T[p ^ 1];

        // ---- phase 1: stage V = 4096/T; zero own slice of Tn
        {
            float4 tv = __ldcg(&((const float4*)Tc)[tid]);
            float4 vv;
            vv.x = 4096.0f / tv.x;  vv.y = 4096.0f / tv.y;
            vv.z = 4096.0f / tv.z;  vv.w = 4096.0f / tv.w;
            ((float4*)sV)[tid] = vv;
            int zi = zs + tid;
            if (zi < ze) __stcg(&Tn[zi], 0.0f);
        }
        gsync(ep);

        // ---- f: warp-per-row, S_i = sum_j K_ij V_j;  U_i = 4096/S_i (block-local)
        {
            float s0 = 0.f, s1 = 0.f, s2 = 0.f, s3 = 0.f;
            bool have = false;
            const uint4* Kr = 0;
            if (wid < SROWS) { Kr = (const uint4*)(sK + wid * N); have = true; }
            else if (wid == SROWS) { Kr = (const uint4*)(d_Kh + (size_t)stray1 * N); have = true; }
            else if (wid == SROWS + 1 && stray2 < N) { Kr = (const uint4*)(d_Kh + (size_t)stray2 * N); have = true; }
            if (have) {
                const float4* V4 = (const float4*)sV;
#pragma unroll 4
                for (int t = ln; t < N / 8; t += 32) {
                    uint4 q = (wid < SROWS) ? Kr[t] : __ldcg(&Kr[t]);
                    float4 va = V4[2 * t];
                    float4 vb = V4[2 * t + 1];
                    s0 = fmaf(bfl(q.x), va.x, s0);
                    s1 = fmaf(bfh(q.x), va.y, s1);
                    s2 = fmaf(bfl(q.y), va.z, s2);
                    s3 = fmaf(bfh(q.y), va.w, s3);
                    s0 = fmaf(bfl(q.z), vb.x, s0);
                    s1 = fmaf(bfh(q.z), vb.y, s1);
                    s2 = fmaf(bfl(q.w), vb.z, s2);
                    s3 = fmaf(bfh(q.w), vb.w, s3);
                }
                float s = (s0 + s1) + (s2 + s3);
                for (int o = 16; o; o >>= 1) s += __shfl_down_sync(0xffffffffu, s, o);
                if (ln == 0) sU[wid] = 4096.0f / s;
            }
        }
        __syncthreads();

        // ---- g: thread owns 4 cols; partial T over own rows; REDG accumulate
        {
            float a0 = 0.f, a1 = 0.f, a2 = 0.f, a3 = 0.f;
#pragma unroll 2
            for (int r = 0; r < SROWS; r++) {
                float u = sU[r];
                uint2 q = ((const uint2*)(sK + r * N))[tid];
                a0 = fmaf(bfl(q.x) * u, 1.0f, a0);
                a1 = fmaf(bfh(q.x) * u, 1.0f, a1);
                a2 = fmaf(bfl(q.y) * u, 1.0f, a2);
                a3 = fmaf(bfh(q.y) * u, 1.0f, a3);
            }
            {
                float u = sU[SROWS];
                uint2 q = __ldcg(&((const uint2*)(d_Kh + (size_t)stray1 * N))[tid]);
                a0 = fmaf(bfl(q.x), u, a0);
                a1 = fmaf(bfh(q.x), u, a1);
                a2 = fmaf(bfl(q.y), u, a2);
                a3 = fmaf(bfh(q.y), u, a3);
            }
            if (stray2 < N) {
                float u = sU[SROWS + 1];
                uint2 q = __ldcg(&((const uint2*)(d_Kh + (size_t)stray2 * N))[tid]);
                a0 = fmaf(bfl(q.x), u, a0);
                a1 = fmaf(bfh(q.x), u, a1);
                a2 = fmaf(bfl(q.y), u, a2);
                a3 = fmaf(bfh(q.y), u, a3);
            }
            atomicAdd(&Tn[4 * tid + 0], a0);
            atomicAdd(&Tn[4 * tid + 1], a1);
            atomicAdd(&Tn[4 * tid + 2], a2);
            atomicAdd(&Tn[4 * tid + 3], a3);
        }
        gsync(ep);
    }

    // ---- final: P = (1/n^2) U K V,  C = -log2(K)/k;  EMD = sum P*C
    {
        const float* Tf = d_T[NITERS & 1];                  // T after iter 299
        float4 tv = __ldcg(&((const float4*)Tf)[tid]);
        float4 vv;
        vv.x = 4096.0f / tv.x;  vv.y = 4096.0f / tv.y;
        vv.z = 4096.0f / tv.z;  vv.w = 4096.0f / tv.w;
        ((float4*)sV)[tid] = vv;
        __syncthreads();

        float s = 0.f;
        bool have = false;
        const uint4* Kr = 0;
        if (wid < SROWS) { Kr = (const uint4*)(sK + wid * N); have = true; }
        else if (wid == SROWS) { Kr = (const uint4*)(d_Kh + (size_t)stray1 * N); have = true; }
        else if (wid == SROWS + 1 && stray2 < N) { Kr = (const uint4*)(d_Kh + (size_t)stray2 * N); have = true; }
        if (have) {
            const float4* V4 = (const float4*)sV;
            float a0 = 0.f, a1 = 0.f, a2 = 0.f, a3 = 0.f;
#pragma unroll 2
            for (int t = ln; t < N / 8; t += 32) {
                uint4 q = (wid < SROWS) ? Kr[t] : __ldcg(&Kr[t]);
                float4 va = V4[2 * t];
                float4 vb = V4[2 * t + 1];
                float b0 = bfl(q.x), b1 = bfh(q.x), b2 = bfl(q.y), b3 = bfh(q.y);
                float b4 = bfl(q.z), b5 = bfh(q.z), b6 = bfl(q.w), b7 = bfh(q.w);
                a0 += (b0 > 0.f) ? -b0 * va.x * __log2f(b0) : 0.f;
                a1 += (b1 > 0.f) ? -b1 * va.y * __log2f(b1) : 0.f;
                a2 += (b2 > 0.f) ? -b2 * va.z * __log2f(b2) : 0.f;
                a3 += (b3 > 0.f) ? -b3 * va.w * __log2f(b3) : 0.f;
                a0 += (b4 > 0.f) ? -b4 * vb.x * __log2f(b4) : 0.f;
                a1 += (b5 > 0.f) ? -b5 * vb.y * __log2f(b5) : 0.f;
                a2 += (b6 > 0.f) ? -b6 * vb.z * __log2f(b6) : 0.f;
                a3 += (b7 > 0.f) ? -b7 * vb.w * __log2f(b7) : 0.f;
            }
            s = ((a0 + a1) + (a2 + a3));
            for (int o = 16; o; o >>= 1) s += __shfl_down_sync(0xffffffffu, s, o);
            if (ln == 0) s *= sU[wid];                      // * U_i
        }
        if (ln == 0) sred[wid] = s;
        __syncthreads();
        if (tid < 32) {
            s = (tid < 28) ? sred[tid] : 0.f;
            for (int o = 16; o; o >>= 1) s += __shfl_down_sync(0xffffffffu, s, o);
            if (tid == 0) atomicAdd(&d_emd, (double)s);
        }
    }
    gsync(ep);
    if (bid == 0 && tid == 0) {
        double emd = __ldcg((const double*)&d_emd);
        out[0] = (float)(emd / ((double)N * (double)N) / (double)d_k);
    }
}

// ---------------------------------------------------------------- launch
extern "C" void kernel_launch(void* const* d_in, const int* in_sizes, int n_in,
                              void* d_out, int out_size) {
    const float* x = (const float*)d_in[0];
    const float* y = (const float*)d_in[1];
    float* out = (float*)d_out;

    cudaFuncSetAttribute(k_persist, cudaFuncAttributeMaxDynamicSharedMemorySize, SMEM_BYTES);

    k_init<<<1, 1>>>();
    k_sum<<<N, 256>>>(x, y);
    k_eps<<<1, 1>>>();
    k_buildK<<<N, 256>>>(x, y);
    k_persist<<<NBLK, TPB, SMEM_BYTES>>>(out);
}

// round 15
// speedup vs baseline: 1.1343x; 1.1343x over previous
#include <cuda_runtime.h>

#define N 4096
#define NN (N * N)
#define NITERS 300
#define NBLK 148
#define TPB 1024

__device__ unsigned short d_Kh[NN];   // K  = bf16(2^(-k*C)), 32MB, row-major
__device__ unsigned short d_KhT[NN];  // K^T, 32MB (coalesced g-pass)
__device__ float  d_F[N];             // potentials, log2 domain
__device__ float  d_G[N];
__device__ double d_csum;
__device__ double d_emd;
__device__ float  d_k;                // log2(e)/eps
__device__ unsigned int g_bar;
__device__ unsigned int g_epoch;

__device__ __forceinline__ float  ldcg(const float* p)   { return __ldcg(p); }
__device__ __forceinline__ uint4  ldcg4(const uint4* p)  { return __ldcg(p); }
__device__ __forceinline__ float  bfl(unsigned u) { return __uint_as_float(u << 16); }
__device__ __forceinline__ float  bfh(unsigned u) { return __uint_as_float(u & 0xFFFF0000u); }

// ---------------------------------------------------------------- init
__global__ void k_init() {
    d_csum  = 0.0;
    d_emd   = 0.0;
    g_bar   = 0u;
    g_epoch = 0u;
}

// ---------------------------------------------------------------- csum; zero F/G
__global__ void k_sum(const float* __restrict__ x, const float* __restrict__ y) {
    __shared__ float sred[8];
    int i = blockIdx.x;
    float x0 = x[3 * i], x1 = x[3 * i + 1], x2 = x[3 * i + 2];
    float xx = x0 * x0 + x1 * x1 + x2 * x2;
    float acc = 0.0f;
    for (int j = threadIdx.x; j < N; j += 256) {
        float y0 = y[3 * j], y1 = y[3 * j + 1], y2 = y[3 * j + 2];
        float yy  = y0 * y0 + y1 * y1 + y2 * y2;
        float dot = x0 * y0 + x1 * y1 + x2 * y2;
        float d2  = xx + yy - 2.0f * dot;
        acc += sqrtf(fmaxf(d2, 0.0f) + 1e-12f);
    }
    for (int o = 16; o; o >>= 1) acc += __shfl_down_sync(0xffffffffu, acc, o);
    if ((threadIdx.x & 31) == 0) sred[threadIdx.x >> 5] = acc;
    __syncthreads();
    if (threadIdx.x < 8) {
        acc = sred[threadIdx.x];
        for (int o = 4; o; o >>= 1) acc += __shfl_down_sync(0xffu, acc, o);
        if (threadIdx.x == 0) atomicAdd(&d_csum, (double)acc);
    }
    if (threadIdx.x == 0) { d_F[i] = 0.0f; d_G[i] = 0.0f; }
}

// ---------------------------------------------------------------- eps -> k
__global__ void k_eps() {
    double mean = d_csum / ((double)N * (double)N);
    d_k = (float)(1.4426950408889634 / (0.02 * mean));
}

// ---------------------------------------------------------------- build: which=0 -> d_Kh[i*N+j]=bf16(2^(-k*dist(x_i,y_j)))
//                                           which=1 -> d_KhT (x/y roles swapped by caller)
// dst resolved IN DEVICE CODE (host cannot pass __device__ symbol addresses!)
__global__ void k_buildK(int which,
                         const float* __restrict__ x, const float* __restrict__ y) {
    unsigned short* dst = which ? d_KhT : d_Kh;
    int i = blockIdx.x;
    float k = d_k;
    float x0 = x[3 * i], x1 = x[3 * i + 1], x2 = x[3 * i + 2];
    float xx = x0 * x0 + x1 * x1 + x2 * x2;
    for (int j = threadIdx.x; j < N; j += 256) {
        float y0 = y[3 * j], y1 = y[3 * j + 1], y2 = y[3 * j + 2];
        float yy  = y0 * y0 + y1 * y1 + y2 * y2;
        float dot = x0 * y0 + x1 * y1 + x2 * y2;
        float d2  = xx + yy - 2.0f * dot;
        float c   = sqrtf(fmaxf(d2, 0.0f) + 1e-12f);
        unsigned u = __float_as_uint(exp2f(-k * c));
        unsigned r = (u + 0x7FFFu + ((u >> 16) & 1u)) >> 16;   // rne bf16
        dst[(size_t)i * N + j] = (unsigned short)r;
    }
}

// ---------------------------------------------------------------- grid barrier (no membar/IVALL)
__device__ __forceinline__ void gsync(unsigned int& ep) {
    __syncthreads();
    if (threadIdx.x == 0) {
        unsigned int t;
        asm volatile("atom.add.release.gpu.u32 %0, [%1], 1;"
                     : "=r"(t) : "l"(&g_bar) : "memory");
        if (t == NBLK - 1) {
            g_bar = 0u;
            asm volatile("st.release.gpu.u32 [%0], %1;"
                         :: "l"(&g_epoch), "r"(ep + 1u) : "memory");
        } else {
            unsigned int v;
            do {
                asm volatile("ld.acquire.gpu.u32 %0, [%1];"
                             : "=r"(v) : "l"(&g_epoch) : "memory");
            } while (v == ep);
        }
    }
    ep++;
    __syncthreads();
}

// ---------------------------------------------------------------- block-local max of staged vector (deterministic, same in all blocks)
__device__ __forceinline__ float blockmax_stage(const float* __restrict__ src,
                                                float* sV, float* sred, float* sMax,
                                                int tid, int wid, int ln) {
    float m = -1e30f;
    for (int j = tid; j < N; j += TPB) {
        float v = __ldcg(&src[j]);
        sV[j] = v;
        m = fmaxf(m, v);
    }
    for (int o = 16; o; o >>= 1) m = fmaxf(m, __shfl_xor_sync(0xffffffffu, m, o));
    if (ln == 0) sred[wid] = m;
    __syncthreads();
    if (tid < 32) {
        float t = sred[tid];
        for (int o = 16; o; o >>= 1) t = fmaxf(t, __shfl_xor_sync(0xffffffffu, t, o));
        if (tid == 0) *sMax = t;
    }
    __syncthreads();
    float h = *sMax;
    for (int j = tid; j < N; j += TPB) sV[j] = exp2f(sV[j] - h);
    __syncthreads();
    return h;
}

// ---------------------------------------------------------------- persistent Sinkhorn + final P*C
__global__ void __launch_bounds__(TPB, 1) k_persist(float* __restrict__ out) {
    __shared__ float sV[N];
    __shared__ float sred[32];
    __shared__ float sMax;
    const int tid = threadIdx.x;
    const int bid = blockIdx.x;
    const int wid = tid >> 5;
    const int ln  = tid & 31;
    const int frow = bid + NBLK * wid;     // round-robin row/col; valid if < N
    unsigned int ep = 0u;

    for (int it = 0; it < NITERS; it++) {
        // ==== f pass: S_i = sum_j K_ij 2^(G_j-Gh);  F_i = 12 - Gh - log2(S_i)
        {
            const float Gh = blockmax_stage(d_G, sV, sred, &sMax, tid, wid, ln);
            if (frow < N) {
                const uint4*  Kr = (const uint4*)(d_Kh + (size_t)frow * N);
                const float4* V4 = (const float4*)sV;
                float s0 = 0.f, s1 = 0.f, s2 = 0.f, s3 = 0.f;
#pragma unroll 4
                for (int t = ln; t < N / 8; t += 32) {
                    uint4  q  = ldcg4(&Kr[t]);
                    float4 va = V4[2 * t];
                    float4 vb = V4[2 * t + 1];
                    s0 = fmaf(bfl(q.x), va.x, s0);
                    s1 = fmaf(bfh(q.x), va.y, s1);
                    s2 = fmaf(bfl(q.y), va.z, s2);
                    s3 = fmaf(bfh(q.y), va.w, s3);
                    s0 = fmaf(bfl(q.z), vb.x, s0);
                    s1 = fmaf(bfh(q.z), vb.y, s1);
                    s2 = fmaf(bfl(q.w), vb.z, s2);
                    s3 = fmaf(bfh(q.w), vb.w, s3);
                }
                float s = (s0 + s1) + (s2 + s3);
                for (int o = 16; o; o >>= 1) s += __shfl_down_sync(0xffffffffu, s, o);
                if (ln == 0) d_F[frow] = 12.0f - Gh - log2f(fmaxf(s, 1e-38f));
            }
        }
        gsync(ep);

        // ==== g pass: T_j = sum_i K^T_ji 2^(F_i-Fh);  G_j = 12 - Fh - log2(T_j)
        {
            const float Fh = blockmax_stage(d_F, sV, sred, &sMax, tid, wid, ln);
            if (frow < N) {
                const uint4*  Kr = (const uint4*)(d_KhT + (size_t)frow * N);
                const float4* V4 = (const float4*)sV;
                float s0 = 0.f, s1 = 0.f, s2 = 0.f, s3 = 0.f;
#pragma unroll 4
                for (int t = ln; t < N / 8; t += 32) {
                    uint4  q  = ldcg4(&Kr[t]);
                    float4 va = V4[2 * t];
                    float4 vb = V4[2 * t + 1];
                    s0 = fmaf(bfl(q.x), va.x, s0);
                    s1 = fmaf(bfh(q.x), va.y, s1);
                    s2 = fmaf(bfl(q.y), va.z, s2);
                    s3 = fmaf(bfh(q.y), va.w, s3);
                    s0 = fmaf(bfl(q.z), vb.x, s0);
                    s1 = fmaf(bfh(q.z), vb.y, s1);
                    s2 = fmaf(bfl(q.w), vb.z, s2);
                    s3 = fmaf(bfh(q.w), vb.w, s3);
                }
                float s = (s0 + s1) + (s2 + s3);
                for (int o = 16; o; o >>= 1) s += __shfl_down_sync(0xffffffffu, s, o);
                if (ln == 0) d_G[frow] = 12.0f - Fh - log2f(fmaxf(s, 1e-38f));
            }
        }
        gsync(ep);
    }

    // ==== final: EMD = sum P*C,  P = U V K 2^(Fh+Gh-24),  C = -log2(K)/k
    {
        const float Gh = blockmax_stage(d_G, sV, sred, &sMax, tid, wid, ln);
        // Fh (no staging needed)
        float m = -1e30f;
        for (int i = tid; i < N; i += TPB) m = fmaxf(m, ldcg(&d_F[i]));
        for (int o = 16; o; o >>= 1) m = fmaxf(m, __shfl_xor_sync(0xffffffffu, m, o));
        if (ln == 0) sred[wid] = m;
        __syncthreads();
        if (tid < 32) {
            float t = sred[tid];
            for (int o = 16; o; o >>= 1) t = fmaxf(t, __shfl_xor_sync(0xffffffffu, t, o));
            if (tid == 0) sMax = t;
        }
        __syncthreads();
        const float Fh = sMax;

        float s = 0.f;
        if (frow < N) {
            const float U = exp2f(ldcg(&d_F[frow]) - Fh);
            const uint4*  Kr = (const uint4*)(d_Kh + (size_t)frow * N);
            const float4* V4 = (const float4*)sV;
            float a0 = 0.f, a1 = 0.f, a2 = 0.f, a3 = 0.f;
#pragma unroll 2
            for (int t = ln; t < N / 8; t += 32) {
                uint4  q  = ldcg4(&Kr[t]);
                float4 va = V4[2 * t];
                float4 vb = V4[2 * t + 1];
                float b0 = bfl(q.x), b1 = bfh(q.x), b2 = bfl(q.y), b3 = bfh(q.y);
                float b4 = bfl(q.z), b5 = bfh(q.z), b6 = bfl(q.w), b7 = bfh(q.w);
                a0 += (b0 > 1e-30f) ? -b0 * va.x * __log2f(b0) : 0.f;
                a1 += (b1 > 1e-30f) ? -b1 * va.y * __log2f(b1) : 0.f;
                a2 += (b2 > 1e-30f) ? -b2 * va.z * __log2f(b2) : 0.f;
                a3 += (b3 > 1e-30f) ? -b3 * va.w * __log2f(b3) : 0.f;
                a0 += (b4 > 1e-30f) ? -b4 * vb.x * __log2f(b4) : 0.f;
                a1 += (b5 > 1e-30f) ? -b5 * vb.y * __log2f(b5) : 0.f;
                a2 += (b6 > 1e-30f) ? -b6 * vb.z * __log2f(b6) : 0.f;
                a3 += (b7 > 1e-30f) ? -b7 * vb.w * __log2f(b7) : 0.f;
            }
            s = U * ((a0 + a1) + (a2 + a3));
            for (int o = 16; o; o >>= 1) s += __shfl_down_sync(0xffffffffu, s, o);
        }
        if (ln == 0) sred[wid] = s;
        __syncthreads();
        if (tid < 32) {
            s = sred[tid];
            for (int o = 16; o; o >>= 1) s += __shfl_down_sync(0xffffffffu, s, o);
            if (tid == 0) atomicAdd(&d_emd, (double)s);
        }
        gsync(ep);
        if (bid == 0 && tid == 0) {
            double emd = __ldcg((const double*)&d_emd);
            out[0] = (float)(emd * exp2((double)Fh + (double)Gh - 24.0) / (double)d_k);
        }
    }
}

// ---------------------------------------------------------------- launch
extern "C" void kernel_launch(void* const* d_in, const int* in_sizes, int n_in,
                              void* d_out, int out_size) {
    const float* x = (const float*)d_in[0];
    const float* y = (const float*)d_in[1];
    float* out = (float*)d_out;

    k_init<<<1, 1>>>();
    k_sum<<<N, 256>>>(x, y);
    k_eps<<<1, 1>>>();
    k_buildK<<<N, 256>>>(0, x, y);   // d_Kh  : rows = x
    k_buildK<<<N, 256>>>(1, y, x);   // d_KhT : rows = y (transpose)
    k_persist<<<NBLK, TPB>>>(out);
}